// round 8
// baseline (speedup 1.0000x reference)
#include <cuda_runtime.h>
#include <cuda_bf16.h>

#define Bsz 64
#define Lsz 1024
#define Dsz 1024
#define Csz 128          // NUM_CLASS + 2
#define STOPTAG 127

// ---------------- scratch (device globals; no allocation allowed) ----------------
__device__ float g_emis[(size_t)Bsz * Lsz * Csz];            // 32 MB
__device__ float g_scores[(size_t)Bsz * (Lsz + 1) * Csz];    // 33.6 MB
__device__ float g_Tt[Csz * Csz];                            // 64 KB transposed T
__device__ int   g_len[Bsz];
__device__ int   g_sel;
__device__ int   g_width;

// ---------------- identify the mask among the two 65536-elem inputs ----------------
__global__ void detect_kernel(const unsigned char* A, const unsigned char* B) {
    __shared__ int bad[6];              // [cand*3 + w], w: 0=u64, 1=u32/f32, 2=u8
    int tid = threadIdx.x;
    if (tid < 6) bad[tid] = 0;
    __syncthreads();
    for (int cand = 0; cand < 2; ++cand) {
        const unsigned char* P = cand ? B : A;
        if (!P) { if (tid == 0) { bad[cand*3+0] = bad[cand*3+1] = bad[cand*3+2] = 1; } continue; }
        const unsigned long long* p8 = (const unsigned long long*)P;
        const unsigned* p4 = (const unsigned*)P;
        for (int i = tid; i < 1024; i += 256) {
            if (p8[i] > 1ull) atomicOr(&bad[cand*3+0], 1);
            unsigned v4 = p4[i];
            if (v4 != 0u && v4 != 1u && v4 != 0x3F800000u) atomicOr(&bad[cand*3+1], 1);
            if (P[i] > 1) atomicOr(&bad[cand*3+2], 1);
        }
    }
    __syncthreads();
    if (tid == 0) {
        int sel = 0, width = 1;
        bool done = false;
        for (int cand = 0; cand < 2 && !done; ++cand) {
            if      (!bad[cand*3+0]) { sel = cand; width = 8; done = true; }
            else if (!bad[cand*3+1]) { sel = cand; width = 4; done = true; }
            else if (!bad[cand*3+2]) { sel = cand; width = 1; done = true; }
        }
        g_sel = sel; g_width = width;
    }
}

// ---------------- sequence lengths ----------------
__global__ void len_kernel(const unsigned char* A, const unsigned char* B) {
    const unsigned char* M = g_sel ? B : A;
    const int w = g_width;
    const int b = blockIdx.x, tid = threadIdx.x;
    int cnt = 0;
    if (w == 8) {
        const unsigned long long* p = ((const unsigned long long*)M) + (size_t)b * Lsz;
        for (int i = tid; i < Lsz; i += 256) cnt += (p[i] != 0ull) ? 1 : 0;
    } else if (w == 4) {
        const unsigned* p = ((const unsigned*)M) + (size_t)b * Lsz;
        for (int i = tid; i < Lsz; i += 256) cnt += (p[i] != 0u) ? 1 : 0;
    } else {
        const unsigned char* p = M + (size_t)b * Lsz;
        for (int i = tid; i < Lsz; i += 256) cnt += (p[i] != 0) ? 1 : 0;
    }
    #pragma unroll
    for (int off = 16; off; off >>= 1) cnt += __shfl_xor_sync(0xffffffffu, cnt, off);
    __shared__ int sr[8];
    if ((tid & 31) == 0) sr[tid >> 5] = cnt;
    __syncthreads();
    if (tid == 0) {
        int s = 0;
        #pragma unroll
        for (int i = 0; i < 8; ++i) s += sr[i];
        g_len[b] = s;
    }
}

// ---------------- transpose T: g_Tt[cur][prev] = T[prev][cur] ----------------
__global__ void prep_kernel(const float* __restrict__ trans) {
    int idx = blockIdx.x * 256 + threadIdx.x;
    int p = idx >> 7, cu = idx & 127;
    g_Tt[cu * Csz + p] = trans[idx];
}

// ---------------- GEMM: emis = x @ W + b  (f32x2 FFMA, pre-duplicated B in smem) ----------------
#define FMA2(d, a, b) asm("fma.rn.f32x2 %0, %1, %2, %0;" : "+l"(d) : "l"(a), "l"(b))
#define PACK2(d, s)   asm("mov.b64 %0, {%1, %1};" : "=l"(d) : "f"(s))
#define UNPACK2(lo, hi, s) asm("mov.b64 {%0, %1}, %2;" : "=f"(lo), "=f"(hi) : "l"(s))

__device__ __forceinline__ unsigned long long dupf(float s) {
    unsigned long long d; PACK2(d, s); return d;
}

#define AS_BYTES (2 * 16 * 132 * 4)          // 16896
#define GEMM_SMEM (AS_BYTES + 2 * 16 * 128 * 8)  // + 32768 = 49664

__global__ __launch_bounds__(256, 2) void gemm_kernel(
    const float* __restrict__ x, const float* __restrict__ W,
    const float* __restrict__ bias)
{
    extern __shared__ __align__(16) unsigned char smemraw[];
    float (*As)[16][132] = reinterpret_cast<float(*)[16][132]>(smemraw);                    // [buf][k][m]
    unsigned long long (*Bd)[16][128] =
        reinterpret_cast<unsigned long long(*)[16][128]>(smemraw + AS_BYTES);               // [buf][k][n] dup pairs

    const int tid = threadIdx.x;
    const int tx = tid & 15;          // n group (8 cols)
    const int ty = tid >> 4;          // m group (8 rows)
    const size_t m_base = (size_t)blockIdx.x * 128;

    const int rA0 = tid >> 2,         qA0 = tid & 3;
    const int rA1 = (tid + 256) >> 2, qA1 = tid & 3;
    const int rB0 = tid >> 5,         cB0 = tid & 31;
    const int rB1 = (tid + 256) >> 5, cB1 = tid & 31;

    unsigned long long acc[4][8];
    #pragma unroll
    for (int i = 0; i < 4; ++i)
        #pragma unroll
        for (int j = 0; j < 8; ++j) acc[i][j] = 0ull;

    // ---- stage 0 ----
    {
        float4 va0 = *(const float4*)(x + (m_base + rA0) * Dsz + (qA0 << 2));
        float4 va1 = *(const float4*)(x + (m_base + rA1) * Dsz + (qA1 << 2));
        float4 vb0 = *(const float4*)(W + (size_t)rB0 * Csz + (cB0 << 2));
        float4 vb1 = *(const float4*)(W + (size_t)rB1 * Csz + (cB1 << 2));
        As[0][qA0 * 4 + 0][rA0] = va0.x; As[0][qA0 * 4 + 1][rA0] = va0.y;
        As[0][qA0 * 4 + 2][rA0] = va0.z; As[0][qA0 * 4 + 3][rA0] = va0.w;
        As[0][qA1 * 4 + 0][rA1] = va1.x; As[0][qA1 * 4 + 1][rA1] = va1.y;
        As[0][qA1 * 4 + 2][rA1] = va1.z; As[0][qA1 * 4 + 3][rA1] = va1.w;
        ulonglong2* d0 = (ulonglong2*)&Bd[0][rB0][cB0 << 2];
        ulonglong2 t0; t0.x = dupf(vb0.x); t0.y = dupf(vb0.y); d0[0] = t0;
        ulonglong2 t1; t1.x = dupf(vb0.z); t1.y = dupf(vb0.w); d0[1] = t1;
        ulonglong2* d1 = (ulonglong2*)&Bd[0][rB1][cB1 << 2];
        ulonglong2 t2; t2.x = dupf(vb1.x); t2.y = dupf(vb1.y); d1[0] = t2;
        ulonglong2 t3; t3.x = dupf(vb1.z); t3.y = dupf(vb1.w); d1[1] = t3;
    }
    __syncthreads();

    const int KT = Dsz / 16;   // 64
    float4 va0, va1, vb0, vb1;
    for (int kt = 0; kt < KT; ++kt) {
        const int buf = kt & 1;
        if (kt < KT - 1) {
            const int k0 = (kt + 1) * 16;
            va0 = *(const float4*)(x + (m_base + rA0) * Dsz + k0 + (qA0 << 2));
            va1 = *(const float4*)(x + (m_base + rA1) * Dsz + k0 + (qA1 << 2));
            vb0 = *(const float4*)(W + (size_t)(k0 + rB0) * Csz + (cB0 << 2));
            vb1 = *(const float4*)(W + (size_t)(k0 + rB1) * Csz + (cB1 << 2));
        }
        #pragma unroll
        for (int k = 0; k < 16; ++k) {
            const float* ap = &As[buf][k][ty * 8];
            ulonglong2 a01 = *(const ulonglong2*)ap;          // m-pairs packed
            ulonglong2 a23 = *(const ulonglong2*)(ap + 4);
            const ulonglong2* bp = (const ulonglong2*)&Bd[buf][k][tx * 8];
            ulonglong2 b01 = bp[0], b23 = bp[1], b45 = bp[2], b67 = bp[3];
            unsigned long long bb[8] = {b01.x, b01.y, b23.x, b23.y, b45.x, b45.y, b67.x, b67.y};
            #pragma unroll
            for (int j = 0; j < 8; ++j) {
                FMA2(acc[0][j], a01.x, bb[j]);
                FMA2(acc[1][j], a01.y, bb[j]);
                FMA2(acc[2][j], a23.x, bb[j]);
                FMA2(acc[3][j], a23.y, bb[j]);
            }
        }
        if (kt < KT - 1) {
            const int nb = buf ^ 1;
            __syncthreads();
            As[nb][qA0 * 4 + 0][rA0] = va0.x; As[nb][qA0 * 4 + 1][rA0] = va0.y;
            As[nb][qA0 * 4 + 2][rA0] = va0.z; As[nb][qA0 * 4 + 3][rA0] = va0.w;
            As[nb][qA1 * 4 + 0][rA1] = va1.x; As[nb][qA1 * 4 + 1][rA1] = va1.y;
            As[nb][qA1 * 4 + 2][rA1] = va1.z; As[nb][qA1 * 4 + 3][rA1] = va1.w;
            ulonglong2* d0 = (ulonglong2*)&Bd[nb][rB0][cB0 << 2];
            ulonglong2 t0; t0.x = dupf(vb0.x); t0.y = dupf(vb0.y); d0[0] = t0;
            ulonglong2 t1; t1.x = dupf(vb0.z); t1.y = dupf(vb0.w); d0[1] = t1;
            ulonglong2* d1 = (ulonglong2*)&Bd[nb][rB1][cB1 << 2];
            ulonglong2 t2; t2.x = dupf(vb1.x); t2.y = dupf(vb1.y); d1[0] = t2;
            ulonglong2 t3; t3.x = dupf(vb1.z); t3.y = dupf(vb1.w); d1[1] = t3;
            __syncthreads();
        }
    }

    float bvv[8];
    #pragma unroll
    for (int j = 0; j < 8; ++j) bvv[j] = bias[tx * 8 + j];
    #pragma unroll
    for (int i = 0; i < 4; ++i) {
        float lo[8], hi[8];
        #pragma unroll
        for (int j = 0; j < 8; ++j) {
            UNPACK2(lo[j], hi[j], acc[i][j]);
            lo[j] += bvv[j]; hi[j] += bvv[j];
        }
        size_t me = m_base + ty * 8 + 2 * i;
        float* oe = g_emis + me * Csz + tx * 8;
        float* oo = g_emis + (me + 1) * Csz + tx * 8;
        *(float4*)oe       = make_float4(lo[0], lo[1], lo[2], lo[3]);
        *(float4*)(oe + 4) = make_float4(lo[4], lo[5], lo[6], lo[7]);
        *(float4*)oo       = make_float4(hi[0], hi[1], hi[2], hi[3]);
        *(float4*)(oo + 4) = make_float4(hi[4], hi[5], hi[6], hi[7]);
    }
}

// ---------------- Viterbi forward v3: 256 threads, pair-split prevs, shfl combine ----------------
// Thread pair (lane 2k, 2k+1) in warp w owns state c = w*16+k; half h = lane&1 scans
// prevs [h*64, h*64+64). max is associative -> bitwise-identical to full scan.
__global__ __launch_bounds__(256, 1) void forward_kernel(const float* __restrict__ trans)
{
    __shared__ __align__(16) float sbuf[2][132];
    const int b = blockIdx.x;
    const int t = threadIdx.x;
    const int w = t >> 5, lane = t & 31;
    const int c = w * 16 + (lane >> 1);
    const int h = lane & 1;
    const int len = g_len[b];

    float treg[64];                             // treg[i] = T[h*64+i][c]
    #pragma unroll
    for (int i = 0; i < 64; ++i) treg[i] = trans[(h * 64 + i) * Csz + c];

    const float* eptr = g_emis + (size_t)b * Lsz * Csz + c;
    float* scrp = g_scores + (size_t)b * (Lsz + 1) * Csz + c;

    // emission prefetch ring, depth 4 (hides 577-cyc DRAM latency)
    float e0 = eptr[0], e1 = eptr[Csz], e2 = eptr[2 * Csz], e3 = eptr[3 * Csz];

    float cur = 0.0f;
    if (h == 0) sbuf[0][c] = 0.0f;
    __syncthreads();

    int par = 0;
    for (int l = 0; l < len; ++l) {
        const float* sb = sbuf[par] + h * 64;
        float m0 = -3.4e38f, m1 = -3.4e38f, m2 = -3.4e38f, m3 = -3.4e38f;
        #pragma unroll
        for (int p = 0; p < 64; p += 4) {
            float4 ss = *(const float4*)(sb + p);
            m0 = fmaxf(m0, ss.x + treg[p + 0]);
            m1 = fmaxf(m1, ss.y + treg[p + 1]);
            m2 = fmaxf(m2, ss.z + treg[p + 2]);
            m3 = fmaxf(m3, ss.w + treg[p + 3]);
        }
        float part = fmaxf(fmaxf(m0, m1), fmaxf(m2, m3));
        float other = __shfl_xor_sync(0xffffffffu, part, 1);
        float full = fmaxf(part, other);
        if (h == 0) {
            scrp[(size_t)l * Csz] = cur;        // entry scores S_l
            cur = full + e0;
            sbuf[par ^ 1][c] = cur;             // S_{l+1} into the other buffer
        }
        e0 = e1; e1 = e2; e2 = e3;
        e3 = (l + 4 < len) ? eptr[(size_t)(l + 4) * Csz] : 0.0f;
        par ^= 1;
        __syncthreads();
    }
    if (h == 0) scrp[(size_t)len * Csz] = cur;  // final scores (pre STOP-transition)
}

// ---------------- backtrack: 8 warps/CTA share smem Tt; redux argmax ----------------
__device__ __forceinline__ unsigned orderable(float f) {
    unsigned u = __float_as_uint(f);
    return (u & 0x80000000u) ? ~u : (u | 0x80000000u);
}

__device__ __forceinline__ int warp_argmax_redux(float bv, int bi) {
    unsigned u = orderable(bv);
    unsigned mx = __reduce_max_sync(0xffffffffu, u);
    unsigned cand = (u == mx) ? (unsigned)bi : 0xffffffffu;
    return (int)__reduce_min_sync(0xffffffffu, cand);    // first occurrence
}

__global__ __launch_bounds__(256, 1) void backtrack_kernel(float* __restrict__ out)
{
    extern __shared__ __align__(16) float Tt[];   // [128][128] = 64 KB
    const int tid = threadIdx.x;
    for (int idx = tid; idx < 128 * 128; idx += 256) Tt[idx] = g_Tt[idx];
    __syncthreads();

    const int w = tid >> 5, lane = tid & 31;
    const int b = blockIdx.x * 8 + w;
    const int len = g_len[b];
    const float* S = g_scores + (size_t)b * (Lsz + 1) * Csz;
    float* orow = out + (size_t)b * Lsz;
    const int i0 = lane * 4;

    for (int l = len + lane; l < Lsz; l += 32) orow[l] = 0.0f;

    float4 fv = *(const float4*)(S + (size_t)len * Csz + i0);
    float4 tv = *(const float4*)(Tt + STOPTAG * Csz + i0);
    float bv; int bi;
    {
        float v0 = fv.x + tv.x, v1 = fv.y + tv.y, v2 = fv.z + tv.z, v3 = fv.w + tv.w;
        bv = v0; bi = i0;
        if (v1 > bv) { bv = v1; bi = i0 + 1; }
        if (v2 > bv) { bv = v2; bi = i0 + 2; }
        if (v3 > bv) { bv = v3; bi = i0 + 3; }
    }
    int cur = warp_argmax_redux(bv, bi);

    float4 r = *(const float4*)(S + (size_t)(len - 1) * Csz + i0);
    for (int l = len - 1; l >= 1; --l) {
        float4 rn;
        if (l > 1) rn = *(const float4*)(S + (size_t)(l - 1) * Csz + i0);
        if (lane == 0) orow[l] = (float)cur;
        float4 t = *(const float4*)(Tt + cur * Csz + i0);
        float v0 = r.x + t.x, v1 = r.y + t.y, v2 = r.z + t.z, v3 = r.w + t.w;
        bv = v0; bi = i0;
        if (v1 > bv) { bv = v1; bi = i0 + 1; }
        if (v2 > bv) { bv = v2; bi = i0 + 2; }
        if (v3 > bv) { bv = v3; bi = i0 + 3; }
        cur = warp_argmax_redux(bv, bi);
        if (l > 1) r = rn;
    }
    if (lane == 0) orow[0] = (float)cur;
}

// ---------------- launch ----------------
extern "C" void kernel_launch(void* const* d_in, const int* in_sizes, int n_in,
                              void* d_out, int out_size)
{
    const float* x = nullptr;
    const float* W = nullptr;
    const float* bias = nullptr;
    const float* trans = nullptr;
    const unsigned char* candA = nullptr;
    const unsigned char* candB = nullptr;
    for (int i = 0; i < n_in; ++i) {
        long long s = in_sizes[i];
        if      (s == (long long)Bsz * Lsz * Dsz) x = (const float*)d_in[i];
        else if (s == (long long)Dsz * Csz)       W = (const float*)d_in[i];
        else if (s == Csz)                        bias = (const float*)d_in[i];
        else if (s == Csz * Csz)                  trans = (const float*)d_in[i];
        else if (s == (long long)Bsz * Lsz) {
            if (!candA) candA = (const unsigned char*)d_in[i];
            else        candB = (const unsigned char*)d_in[i];
        }
    }
    float* out = (float*)d_out;

    cudaFuncSetAttribute(gemm_kernel,
                         cudaFuncAttributeMaxDynamicSharedMemorySize, GEMM_SMEM);
    cudaFuncSetAttribute(backtrack_kernel,
                         cudaFuncAttributeMaxDynamicSharedMemorySize, 128 * 128 * 4);

    detect_kernel<<<1, 256>>>(candA, candB);
    len_kernel<<<Bsz, 256>>>(candA, candB);
    prep_kernel<<<Csz * Csz / 256, 256>>>(trans);
    gemm_kernel<<<(Bsz * Lsz) / 128, 256, GEMM_SMEM>>>(x, W, bias);
    forward_kernel<<<Bsz, 256>>>(trans);
    backtrack_kernel<<<Bsz / 8, 256, 128 * 128 * 4>>>(out);
}

// round 9
// speedup vs baseline: 1.2716x; 1.2716x over previous
#include <cuda_runtime.h>
#include <cuda_bf16.h>

#define Bsz 64
#define Lsz 1024
#define Dsz 1024
#define Csz 128          // NUM_CLASS + 2
#define STOPTAG 127

// ---------------- scratch (device globals; no allocation allowed) ----------------
__device__ float g_emis[(size_t)Bsz * Lsz * Csz];            // 32 MB
__device__ float g_scores[(size_t)Bsz * (Lsz + 1) * Csz];    // 33.6 MB
__device__ float g_Tt[Csz * Csz];                            // 64 KB transposed T
__device__ int   g_len[Bsz];
__device__ int   g_sel;
__device__ int   g_width;

// ---------------- identify the mask among the two 65536-elem inputs ----------------
__global__ void detect_kernel(const unsigned char* A, const unsigned char* B) {
    __shared__ int bad[6];              // [cand*3 + w], w: 0=u64, 1=u32/f32, 2=u8
    int tid = threadIdx.x;
    if (tid < 6) bad[tid] = 0;
    __syncthreads();
    for (int cand = 0; cand < 2; ++cand) {
        const unsigned char* P = cand ? B : A;
        if (!P) { if (tid == 0) { bad[cand*3+0] = bad[cand*3+1] = bad[cand*3+2] = 1; } continue; }
        const unsigned long long* p8 = (const unsigned long long*)P;
        const unsigned* p4 = (const unsigned*)P;
        for (int i = tid; i < 1024; i += 256) {
            if (p8[i] > 1ull) atomicOr(&bad[cand*3+0], 1);
            unsigned v4 = p4[i];
            if (v4 != 0u && v4 != 1u && v4 != 0x3F800000u) atomicOr(&bad[cand*3+1], 1);
            if (P[i] > 1) atomicOr(&bad[cand*3+2], 1);
        }
    }
    __syncthreads();
    if (tid == 0) {
        int sel = 0, width = 1;
        bool done = false;
        for (int cand = 0; cand < 2 && !done; ++cand) {
            if      (!bad[cand*3+0]) { sel = cand; width = 8; done = true; }
            else if (!bad[cand*3+1]) { sel = cand; width = 4; done = true; }
            else if (!bad[cand*3+2]) { sel = cand; width = 1; done = true; }
        }
        g_sel = sel; g_width = width;
    }
}

// ---------------- sequence lengths ----------------
__global__ void len_kernel(const unsigned char* A, const unsigned char* B) {
    const unsigned char* M = g_sel ? B : A;
    const int w = g_width;
    const int b = blockIdx.x, tid = threadIdx.x;
    int cnt = 0;
    if (w == 8) {
        const unsigned long long* p = ((const unsigned long long*)M) + (size_t)b * Lsz;
        for (int i = tid; i < Lsz; i += 256) cnt += (p[i] != 0ull) ? 1 : 0;
    } else if (w == 4) {
        const unsigned* p = ((const unsigned*)M) + (size_t)b * Lsz;
        for (int i = tid; i < Lsz; i += 256) cnt += (p[i] != 0u) ? 1 : 0;
    } else {
        const unsigned char* p = M + (size_t)b * Lsz;
        for (int i = tid; i < Lsz; i += 256) cnt += (p[i] != 0) ? 1 : 0;
    }
    #pragma unroll
    for (int off = 16; off; off >>= 1) cnt += __shfl_xor_sync(0xffffffffu, cnt, off);
    __shared__ int sr[8];
    if ((tid & 31) == 0) sr[tid >> 5] = cnt;
    __syncthreads();
    if (tid == 0) {
        int s = 0;
        #pragma unroll
        for (int i = 0; i < 8; ++i) s += sr[i];
        g_len[b] = s;
    }
}

// ---------------- transpose T: g_Tt[cur][prev] = T[prev][cur] ----------------
__global__ void prep_kernel(const float* __restrict__ trans) {
    int idx = blockIdx.x * 256 + threadIdx.x;
    int p = idx >> 7, cu = idx & 127;
    g_Tt[cu * Csz + p] = trans[idx];
}

// ---------------- GEMM (round-6 version, verbatim: 387us, regs fit exactly) ----------------
#define FMA2(d, a, b) asm("fma.rn.f32x2 %0, %1, %2, %0;" : "+l"(d) : "l"(a), "l"(b))
#define PACK2(d, s)   asm("mov.b64 %0, {%1, %1};" : "=l"(d) : "f"(s))
#define UNPACK2(lo, hi, s) asm("mov.b64 {%0, %1}, %2;" : "=f"(lo), "=f"(hi) : "l"(s))

__global__ __launch_bounds__(256, 2) void gemm_kernel(
    const float* __restrict__ x, const float* __restrict__ W,
    const float* __restrict__ bias)
{
    __shared__ __align__(16) float As[2][16][132];   // [k][m], padded
    __shared__ __align__(16) float Bs[2][16][128];   // [k][n]

    const int tid = threadIdx.x;
    const int tx = tid & 15;          // n group
    const int ty = tid >> 4;          // m group
    const size_t m_base = (size_t)blockIdx.x * 128;

    const int rA0 = tid >> 2,         qA0 = tid & 3;
    const int rA1 = (tid + 256) >> 2, qA1 = tid & 3;
    const int rB0 = tid >> 5,         cB0 = tid & 31;
    const int rB1 = (tid + 256) >> 5, cB1 = tid & 31;

    unsigned long long acc[4][8];
    #pragma unroll
    for (int i = 0; i < 4; ++i)
        #pragma unroll
        for (int j = 0; j < 8; ++j) acc[i][j] = 0ull;

    {
        float4 va0 = *(const float4*)(x + (m_base + rA0) * Dsz + (qA0 << 2));
        float4 va1 = *(const float4*)(x + (m_base + rA1) * Dsz + (qA1 << 2));
        float4 vb0 = *(const float4*)(W + (size_t)rB0 * Csz + (cB0 << 2));
        float4 vb1 = *(const float4*)(W + (size_t)rB1 * Csz + (cB1 << 2));
        As[0][qA0 * 4 + 0][rA0] = va0.x; As[0][qA0 * 4 + 1][rA0] = va0.y;
        As[0][qA0 * 4 + 2][rA0] = va0.z; As[0][qA0 * 4 + 3][rA0] = va0.w;
        As[0][qA1 * 4 + 0][rA1] = va1.x; As[0][qA1 * 4 + 1][rA1] = va1.y;
        As[0][qA1 * 4 + 2][rA1] = va1.z; As[0][qA1 * 4 + 3][rA1] = va1.w;
        *(float4*)&Bs[0][rB0][cB0 << 2] = vb0;
        *(float4*)&Bs[0][rB1][cB1 << 2] = vb1;
    }
    __syncthreads();

    const int KT = Dsz / 16;   // 64
    float4 va0, va1, vb0, vb1;
    for (int kt = 0; kt < KT; ++kt) {
        const int buf = kt & 1;
        if (kt < KT - 1) {
            const int k0 = (kt + 1) * 16;
            va0 = *(const float4*)(x + (m_base + rA0) * Dsz + k0 + (qA0 << 2));
            va1 = *(const float4*)(x + (m_base + rA1) * Dsz + k0 + (qA1 << 2));
            vb0 = *(const float4*)(W + (size_t)(k0 + rB0) * Csz + (cB0 << 2));
            vb1 = *(const float4*)(W + (size_t)(k0 + rB1) * Csz + (cB1 << 2));
        }
        #pragma unroll
        for (int k = 0; k < 16; ++k) {
            const float* ap = &As[buf][k][ty * 8];
            ulonglong2 a01 = *(const ulonglong2*)ap;          // m-pairs packed
            ulonglong2 a23 = *(const ulonglong2*)(ap + 4);
            const float* bp = &Bs[buf][k][tx * 8];
            float4 b03 = *(const float4*)bp;
            float4 b47 = *(const float4*)(bp + 4);
            float bv[8] = {b03.x, b03.y, b03.z, b03.w, b47.x, b47.y, b47.z, b47.w};
            #pragma unroll
            for (int j = 0; j < 8; ++j) {
                unsigned long long bb;
                PACK2(bb, bv[j]);
                FMA2(acc[0][j], a01.x, bb);
                FMA2(acc[1][j], a01.y, bb);
                FMA2(acc[2][j], a23.x, bb);
                FMA2(acc[3][j], a23.y, bb);
            }
        }
        if (kt < KT - 1) {
            const int nb = buf ^ 1;
            __syncthreads();
            As[nb][qA0 * 4 + 0][rA0] = va0.x; As[nb][qA0 * 4 + 1][rA0] = va0.y;
            As[nb][qA0 * 4 + 2][rA0] = va0.z; As[nb][qA0 * 4 + 3][rA0] = va0.w;
            As[nb][qA1 * 4 + 0][rA1] = va1.x; As[nb][qA1 * 4 + 1][rA1] = va1.y;
            As[nb][qA1 * 4 + 2][rA1] = va1.z; As[nb][qA1 * 4 + 3][rA1] = va1.w;
            *(float4*)&Bs[nb][rB0][cB0 << 2] = vb0;
            *(float4*)&Bs[nb][rB1][cB1 << 2] = vb1;
            __syncthreads();
        }
    }

    float bvv[8];
    #pragma unroll
    for (int j = 0; j < 8; ++j) bvv[j] = bias[tx * 8 + j];
    #pragma unroll
    for (int i = 0; i < 4; ++i) {
        float lo[8], hi[8];
        #pragma unroll
        for (int j = 0; j < 8; ++j) {
            UNPACK2(lo[j], hi[j], acc[i][j]);
            lo[j] += bvv[j]; hi[j] += bvv[j];
        }
        size_t me = m_base + ty * 8 + 2 * i;
        float* oe = g_emis + me * Csz + tx * 8;
        float* oo = g_emis + (me + 1) * Csz + tx * 8;
        *(float4*)oe       = make_float4(lo[0], lo[1], lo[2], lo[3]);
        *(float4*)(oe + 4) = make_float4(lo[4], lo[5], lo[6], lo[7]);
        *(float4*)oo       = make_float4(hi[0], hi[1], hi[2], hi[3]);
        *(float4*)(oo + 4) = make_float4(hi[4], hi[5], hi[6], hi[7]);
    }
}

// ---------------- Viterbi forward v3: 256 threads, pair-split prevs, shfl combine ----------------
// Thread pair (lane 2k, 2k+1) in warp w owns state c = w*16+k; half h = lane&1 scans
// prevs [h*64, h*64+64). max is associative -> bitwise-identical to full scan.
__global__ __launch_bounds__(256, 1) void forward_kernel(const float* __restrict__ trans)
{
    __shared__ __align__(16) float sbuf[2][132];
    const int b = blockIdx.x;
    const int t = threadIdx.x;
    const int w = t >> 5, lane = t & 31;
    const int c = w * 16 + (lane >> 1);
    const int h = lane & 1;
    const int len = g_len[b];

    float treg[64];                             // treg[i] = T[h*64+i][c]
    #pragma unroll
    for (int i = 0; i < 64; ++i) treg[i] = trans[(h * 64 + i) * Csz + c];

    const float* eptr = g_emis + (size_t)b * Lsz * Csz + c;
    float* scrp = g_scores + (size_t)b * (Lsz + 1) * Csz + c;

    // emission prefetch ring, depth 4 (hides L2/DRAM latency behind ~4 steps)
    float e0 = eptr[0], e1 = eptr[Csz], e2 = eptr[2 * Csz], e3 = eptr[3 * Csz];

    float cur = 0.0f;
    if (h == 0) sbuf[0][c] = 0.0f;
    __syncthreads();

    int par = 0;
    for (int l = 0; l < len; ++l) {
        const float* sb = sbuf[par] + h * 64;
        float m0 = -3.4e38f, m1 = -3.4e38f, m2 = -3.4e38f, m3 = -3.4e38f;
        #pragma unroll
        for (int p = 0; p < 64; p += 4) {
            float4 ss = *(const float4*)(sb + p);
            m0 = fmaxf(m0, ss.x + treg[p + 0]);
            m1 = fmaxf(m1, ss.y + treg[p + 1]);
            m2 = fmaxf(m2, ss.z + treg[p + 2]);
            m3 = fmaxf(m3, ss.w + treg[p + 3]);
        }
        float part = fmaxf(fmaxf(m0, m1), fmaxf(m2, m3));
        float other = __shfl_xor_sync(0xffffffffu, part, 1);
        float full = fmaxf(part, other);
        if (h == 0) {
            scrp[(size_t)l * Csz] = cur;        // entry scores S_l
            cur = full + e0;
            sbuf[par ^ 1][c] = cur;             // S_{l+1} into the other buffer
        }
        e0 = e1; e1 = e2; e2 = e3;
        e3 = (l + 4 < len) ? eptr[(size_t)(l + 4) * Csz] : 0.0f;
        par ^= 1;
        __syncthreads();
    }
    if (h == 0) scrp[(size_t)len * Csz] = cur;  // final scores (pre STOP-transition)
}

// ---------------- backtrack: 8 warps/CTA share smem Tt; redux argmax ----------------
__device__ __forceinline__ unsigned orderable(float f) {
    unsigned u = __float_as_uint(f);
    return (u & 0x80000000u) ? ~u : (u | 0x80000000u);
}

__device__ __forceinline__ int warp_argmax_redux(float bv, int bi) {
    unsigned u = orderable(bv);
    unsigned mx = __reduce_max_sync(0xffffffffu, u);
    unsigned cand = (u == mx) ? (unsigned)bi : 0xffffffffu;
    return (int)__reduce_min_sync(0xffffffffu, cand);    // first occurrence
}

__global__ __launch_bounds__(256, 1) void backtrack_kernel(float* __restrict__ out)
{
    extern __shared__ __align__(16) float Tt[];   // [128][128] = 64 KB
    const int tid = threadIdx.x;
    for (int idx = tid; idx < 128 * 128; idx += 256) Tt[idx] = g_Tt[idx];
    __syncthreads();

    const int w = tid >> 5, lane = tid & 31;
    const int b = blockIdx.x * 8 + w;
    const int len = g_len[b];
    const float* S = g_scores + (size_t)b * (Lsz + 1) * Csz;
    float* orow = out + (size_t)b * Lsz;
    const int i0 = lane * 4;

    for (int l = len + lane; l < Lsz; l += 32) orow[l] = 0.0f;

    float4 fv = *(const float4*)(S + (size_t)len * Csz + i0);
    float4 tv = *(const float4*)(Tt + STOPTAG * Csz + i0);
    float bv; int bi;
    {
        float v0 = fv.x + tv.x, v1 = fv.y + tv.y, v2 = fv.z + tv.z, v3 = fv.w + tv.w;
        bv = v0; bi = i0;
        if (v1 > bv) { bv = v1; bi = i0 + 1; }
        if (v2 > bv) { bv = v2; bi = i0 + 2; }
        if (v3 > bv) { bv = v3; bi = i0 + 3; }
    }
    int cur = warp_argmax_redux(bv, bi);

    float4 r = *(const float4*)(S + (size_t)(len - 1) * Csz + i0);
    for (int l = len - 1; l >= 1; --l) {
        float4 rn;
        if (l > 1) rn = *(const float4*)(S + (size_t)(l - 1) * Csz + i0);
        if (lane == 0) orow[l] = (float)cur;
        float4 t = *(const float4*)(Tt + cur * Csz + i0);
        float v0 = r.x + t.x, v1 = r.y + t.y, v2 = r.z + t.z, v3 = r.w + t.w;
        bv = v0; bi = i0;
        if (v1 > bv) { bv = v1; bi = i0 + 1; }
        if (v2 > bv) { bv = v2; bi = i0 + 2; }
        if (v3 > bv) { bv = v3; bi = i0 + 3; }
        cur = warp_argmax_redux(bv, bi);
        if (l > 1) r = rn;
    }
    if (lane == 0) orow[0] = (float)cur;
}

// ---------------- launch ----------------
extern "C" void kernel_launch(void* const* d_in, const int* in_sizes, int n_in,
                              void* d_out, int out_size)
{
    const float* x = nullptr;
    const float* W = nullptr;
    const float* bias = nullptr;
    const float* trans = nullptr;
    const unsigned char* candA = nullptr;
    const unsigned char* candB = nullptr;
    for (int i = 0; i < n_in; ++i) {
        long long s = in_sizes[i];
        if      (s == (long long)Bsz * Lsz * Dsz) x = (const float*)d_in[i];
        else if (s == (long long)Dsz * Csz)       W = (const float*)d_in[i];
        else if (s == Csz)                        bias = (const float*)d_in[i];
        else if (s == Csz * Csz)                  trans = (const float*)d_in[i];
        else if (s == (long long)Bsz * Lsz) {
            if (!candA) candA = (const unsigned char*)d_in[i];
            else        candB = (const unsigned char*)d_in[i];
        }
    }
    float* out = (float*)d_out;

    cudaFuncSetAttribute(backtrack_kernel,
                         cudaFuncAttributeMaxDynamicSharedMemorySize, 128 * 128 * 4);

    detect_kernel<<<1, 256>>>(candA, candB);
    len_kernel<<<Bsz, 256>>>(candA, candB);
    prep_kernel<<<Csz * Csz / 256, 256>>>(trans);
    gemm_kernel<<<(Bsz * Lsz) / 128, 256>>>(x, W, bias);
    forward_kernel<<<Bsz, 256>>>(trans);
    backtrack_kernel<<<Bsz / 8, 256, 128 * 128 * 4>>>(out);
}

// round 11
// speedup vs baseline: 1.6880x; 1.3275x over previous
#include <cuda_runtime.h>
#include <cuda_bf16.h>

#define Bsz 64
#define Lsz 1024
#define Dsz 1024
#define Csz 128          // NUM_CLASS + 2
#define STOPTAG 127

// ---------------- scratch (device globals; no allocation allowed) ----------------
__device__ float g_emis[(size_t)Bsz * Lsz * Csz];            // 32 MB
__device__ float g_scores[(size_t)Bsz * (Lsz + 1) * Csz];    // 33.6 MB
__device__ float g_Tt[Csz * Csz];                            // 64 KB transposed T
__device__ int   g_len[Bsz];
__device__ int   g_sel;
__device__ int   g_width;

// ---------------- identify the mask among the two 65536-elem inputs ----------------
__global__ void detect_kernel(const unsigned char* A, const unsigned char* B) {
    __shared__ int bad[6];              // [cand*3 + w], w: 0=u64, 1=u32/f32, 2=u8
    int tid = threadIdx.x;
    if (tid < 6) bad[tid] = 0;
    __syncthreads();
    for (int cand = 0; cand < 2; ++cand) {
        const unsigned char* P = cand ? B : A;
        if (!P) { if (tid == 0) { bad[cand*3+0] = bad[cand*3+1] = bad[cand*3+2] = 1; } continue; }
        const unsigned long long* p8 = (const unsigned long long*)P;
        const unsigned* p4 = (const unsigned*)P;
        for (int i = tid; i < 1024; i += 256) {
            if (p8[i] > 1ull) atomicOr(&bad[cand*3+0], 1);
            unsigned v4 = p4[i];
            if (v4 != 0u && v4 != 1u && v4 != 0x3F800000u) atomicOr(&bad[cand*3+1], 1);
            if (P[i] > 1) atomicOr(&bad[cand*3+2], 1);
        }
    }
    __syncthreads();
    if (tid == 0) {
        int sel = 0, width = 1;
        bool done = false;
        for (int cand = 0; cand < 2 && !done; ++cand) {
            if      (!bad[cand*3+0]) { sel = cand; width = 8; done = true; }
            else if (!bad[cand*3+1]) { sel = cand; width = 4; done = true; }
            else if (!bad[cand*3+2]) { sel = cand; width = 1; done = true; }
        }
        g_sel = sel; g_width = width;
    }
}

// ---------------- sequence lengths ----------------
__global__ void len_kernel(const unsigned char* A, const unsigned char* B) {
    const unsigned char* M = g_sel ? B : A;
    const int w = g_width;
    const int b = blockIdx.x, tid = threadIdx.x;
    int cnt = 0;
    if (w == 8) {
        const unsigned long long* p = ((const unsigned long long*)M) + (size_t)b * Lsz;
        for (int i = tid; i < Lsz; i += 256) cnt += (p[i] != 0ull) ? 1 : 0;
    } else if (w == 4) {
        const unsigned* p = ((const unsigned*)M) + (size_t)b * Lsz;
        for (int i = tid; i < Lsz; i += 256) cnt += (p[i] != 0u) ? 1 : 0;
    } else {
        const unsigned char* p = M + (size_t)b * Lsz;
        for (int i = tid; i < Lsz; i += 256) cnt += (p[i] != 0) ? 1 : 0;
    }
    #pragma unroll
    for (int off = 16; off; off >>= 1) cnt += __shfl_xor_sync(0xffffffffu, cnt, off);
    __shared__ int sr[8];
    if ((tid & 31) == 0) sr[tid >> 5] = cnt;
    __syncthreads();
    if (tid == 0) {
        int s = 0;
        #pragma unroll
        for (int i = 0; i < 8; ++i) s += sr[i];
        g_len[b] = s;
    }
}

// ---------------- transpose T: g_Tt[cur][prev] = T[prev][cur] ----------------
__global__ void prep_kernel(const float* __restrict__ trans) {
    int idx = blockIdx.x * 256 + threadIdx.x;
    int p = idx >> 7, cu = idx & 127;
    g_Tt[cu * Csz + p] = trans[idx];
}

// ---------------- GEMM (round-6 version, verbatim) ----------------
#define FMA2(d, a, b) asm("fma.rn.f32x2 %0, %1, %2, %0;" : "+l"(d) : "l"(a), "l"(b))
#define PACK2(d, s)   asm("mov.b64 %0, {%1, %1};" : "=l"(d) : "f"(s))
#define UNPACK2(lo, hi, s) asm("mov.b64 {%0, %1}, %2;" : "=f"(lo), "=f"(hi) : "l"(s))

__global__ __launch_bounds__(256, 2) void gemm_kernel(
    const float* __restrict__ x, const float* __restrict__ W,
    const float* __restrict__ bias)
{
    __shared__ __align__(16) float As[2][16][132];   // [k][m], padded
    __shared__ __align__(16) float Bs[2][16][128];   // [k][n]

    const int tid = threadIdx.x;
    const int tx = tid & 15;
    const int ty = tid >> 4;
    const size_t m_base = (size_t)blockIdx.x * 128;

    const int rA0 = tid >> 2,         qA0 = tid & 3;
    const int rA1 = (tid + 256) >> 2, qA1 = tid & 3;
    const int rB0 = tid >> 5,         cB0 = tid & 31;
    const int rB1 = (tid + 256) >> 5, cB1 = tid & 31;

    unsigned long long acc[4][8];
    #pragma unroll
    for (int i = 0; i < 4; ++i)
        #pragma unroll
        for (int j = 0; j < 8; ++j) acc[i][j] = 0ull;

    {
        float4 va0 = *(const float4*)(x + (m_base + rA0) * Dsz + (qA0 << 2));
        float4 va1 = *(const float4*)(x + (m_base + rA1) * Dsz + (qA1 << 2));
        float4 vb0 = *(const float4*)(W + (size_t)rB0 * Csz + (cB0 << 2));
        float4 vb1 = *(const float4*)(W + (size_t)rB1 * Csz + (cB1 << 2));
        As[0][qA0 * 4 + 0][rA0] = va0.x; As[0][qA0 * 4 + 1][rA0] = va0.y;
        As[0][qA0 * 4 + 2][rA0] = va0.z; As[0][qA0 * 4 + 3][rA0] = va0.w;
        As[0][qA1 * 4 + 0][rA1] = va1.x; As[0][qA1 * 4 + 1][rA1] = va1.y;
        As[0][qA1 * 4 + 2][rA1] = va1.z; As[0][qA1 * 4 + 3][rA1] = va1.w;
        *(float4*)&Bs[0][rB0][cB0 << 2] = vb0;
        *(float4*)&Bs[0][rB1][cB1 << 2] = vb1;
    }
    __syncthreads();

    const int KT = Dsz / 16;   // 64
    float4 va0, va1, vb0, vb1;
    for (int kt = 0; kt < KT; ++kt) {
        const int buf = kt & 1;
        if (kt < KT - 1) {
            const int k0 = (kt + 1) * 16;
            va0 = *(const float4*)(x + (m_base + rA0) * Dsz + k0 + (qA0 << 2));
            va1 = *(const float4*)(x + (m_base + rA1) * Dsz + k0 + (qA1 << 2));
            vb0 = *(const float4*)(W + (size_t)(k0 + rB0) * Csz + (cB0 << 2));
            vb1 = *(const float4*)(W + (size_t)(k0 + rB1) * Csz + (cB1 << 2));
        }
        #pragma unroll
        for (int k = 0; k < 16; ++k) {
            const float* ap = &As[buf][k][ty * 8];
            ulonglong2 a01 = *(const ulonglong2*)ap;
            ulonglong2 a23 = *(const ulonglong2*)(ap + 4);
            const float* bp = &Bs[buf][k][tx * 8];
            float4 b03 = *(const float4*)bp;
            float4 b47 = *(const float4*)(bp + 4);
            float bv[8] = {b03.x, b03.y, b03.z, b03.w, b47.x, b47.y, b47.z, b47.w};
            #pragma unroll
            for (int j = 0; j < 8; ++j) {
                unsigned long long bb;
                PACK2(bb, bv[j]);
                FMA2(acc[0][j], a01.x, bb);
                FMA2(acc[1][j], a01.y, bb);
                FMA2(acc[2][j], a23.x, bb);
                FMA2(acc[3][j], a23.y, bb);
            }
        }
        if (kt < KT - 1) {
            const int nb = buf ^ 1;
            __syncthreads();
            As[nb][qA0 * 4 + 0][rA0] = va0.x; As[nb][qA0 * 4 + 1][rA0] = va0.y;
            As[nb][qA0 * 4 + 2][rA0] = va0.z; As[nb][qA0 * 4 + 3][rA0] = va0.w;
            As[nb][qA1 * 4 + 0][rA1] = va1.x; As[nb][qA1 * 4 + 1][rA1] = va1.y;
            As[nb][qA1 * 4 + 2][rA1] = va1.z; As[nb][qA1 * 4 + 3][rA1] = va1.w;
            *(float4*)&Bs[nb][rB0][cB0 << 2] = vb0;
            *(float4*)&Bs[nb][rB1][cB1 << 2] = vb1;
            __syncthreads();
        }
    }

    float bvv[8];
    #pragma unroll
    for (int j = 0; j < 8; ++j) bvv[j] = bias[tx * 8 + j];
    #pragma unroll
    for (int i = 0; i < 4; ++i) {
        float lo[8], hi[8];
        #pragma unroll
        for (int j = 0; j < 8; ++j) {
            UNPACK2(lo[j], hi[j], acc[i][j]);
            lo[j] += bvv[j]; hi[j] += bvv[j];
        }
        size_t me = m_base + ty * 8 + 2 * i;
        float* oe = g_emis + me * Csz + tx * 8;
        float* oo = g_emis + (me + 1) * Csz + tx * 8;
        *(float4*)oe       = make_float4(lo[0], lo[1], lo[2], lo[3]);
        *(float4*)(oe + 4) = make_float4(lo[4], lo[5], lo[6], lo[7]);
        *(float4*)oo       = make_float4(hi[0], hi[1], hi[2], hi[3]);
        *(float4*)(oo + 4) = make_float4(hi[4], hi[5], hi[6], hi[7]);
    }
}

// ---------------- Viterbi forward v2': 128 threads, 8 max-accumulators ----------------
// Thread c owns cur-state c; 8 independent FADD->FMNMX chains of 16 (was 4x32)
// halve the per-step critical path. max is associative: result bitwise-identical.
__global__ __launch_bounds__(128, 1) void forward_kernel(const float* __restrict__ trans)
{
    __shared__ __align__(16) float sbuf[264];   // two buffers, 132-float pitch
    const int b = blockIdx.x;
    const int c = threadIdx.x;
    const int len = g_len[b];

    float treg[128];                            // treg[p] = T[p][c]
    #pragma unroll
    for (int p = 0; p < 128; ++p) treg[p] = trans[p * Csz + c];

    float cur = 0.0f;
    const float* eptr = g_emis + (size_t)b * Lsz * Csz + c;
    float* scrp = g_scores + (size_t)b * (Lsz + 1) * Csz + c;

    // emission prefetch ring, depth 2 (covers ~250-cyc L2 hit)
    float e0 = eptr[0];
    float e1 = eptr[Csz];

    int par = 0;
    for (int l = 0; l < len; ++l) {
        float* sb = sbuf + (par ? 132 : 0);
        sb[c] = cur;
        scrp[(size_t)l * Csz] = cur;            // entry scores S_l
        __syncthreads();
        float e = e0;
        e0 = e1;
        if (l + 2 < len) e1 = eptr[(size_t)(l + 2) * Csz];
        float m0 = -3.4e38f, m1 = -3.4e38f, m2 = -3.4e38f, m3 = -3.4e38f;
        float m4 = -3.4e38f, m5 = -3.4e38f, m6 = -3.4e38f, m7 = -3.4e38f;
        #pragma unroll
        for (int p = 0; p < 128; p += 8) {
            float4 s0 = *(const float4*)(sb + p);
            float4 s1 = *(const float4*)(sb + p + 4);
            m0 = fmaxf(m0, s0.x + treg[p + 0]);
            m1 = fmaxf(m1, s0.y + treg[p + 1]);
            m2 = fmaxf(m2, s0.z + treg[p + 2]);
            m3 = fmaxf(m3, s0.w + treg[p + 3]);
            m4 = fmaxf(m4, s1.x + treg[p + 4]);
            m5 = fmaxf(m5, s1.y + treg[p + 5]);
            m6 = fmaxf(m6, s1.z + treg[p + 6]);
            m7 = fmaxf(m7, s1.w + treg[p + 7]);
        }
        float ma = fmaxf(fmaxf(m0, m1), fmaxf(m2, m3));
        float mb = fmaxf(fmaxf(m4, m5), fmaxf(m6, m7));
        cur = fmaxf(ma, mb) + e;
        par ^= 1;
    }
    scrp[(size_t)len * Csz] = cur;              // final scores (pre STOP-transition)
}

// ---------------- backtrack: 8 warps/CTA share smem Tt; redux argmax; S-ring depth 3 ----------------
__device__ __forceinline__ unsigned orderable(float f) {
    unsigned u = __float_as_uint(f);
    return (u & 0x80000000u) ? ~u : (u | 0x80000000u);
}

__device__ __forceinline__ int warp_argmax_redux(float bv, int bi) {
    unsigned u = orderable(bv);
    unsigned mx = __reduce_max_sync(0xffffffffu, u);
    unsigned cand = (u == mx) ? (unsigned)bi : 0xffffffffu;
    return (int)__reduce_min_sync(0xffffffffu, cand);    // first occurrence
}

__global__ __launch_bounds__(256, 1) void backtrack_kernel(float* __restrict__ out)
{
    extern __shared__ __align__(16) float Tt[];   // [128][128] = 64 KB
    const int tid = threadIdx.x;
    for (int idx = tid; idx < 128 * 128; idx += 256) Tt[idx] = g_Tt[idx];
    __syncthreads();

    const int w = tid >> 5, lane = tid & 31;
    const int b = blockIdx.x * 8 + w;
    const int len = g_len[b];
    const float* S = g_scores + (size_t)b * (Lsz + 1) * Csz;
    float* orow = out + (size_t)b * Lsz;
    const int i0 = lane * 4;

    for (int l = len + lane; l < Lsz; l += 32) orow[l] = 0.0f;

    // last tag: argmax_c( final[c] + T[c][STOP] );  Tt[STOP][c] = T[c][STOP]
    float4 fv = *(const float4*)(S + (size_t)len * Csz + i0);
    float4 tv = *(const float4*)(Tt + STOPTAG * Csz + i0);
    float bv; int bi;
    {
        float v0 = fv.x + tv.x, v1 = fv.y + tv.y, v2 = fv.z + tv.z, v3 = fv.w + tv.w;
        bv = v0; bi = i0;
        if (v1 > bv) { bv = v1; bi = i0 + 1; }
        if (v2 > bv) { bv = v2; bi = i0 + 2; }
        if (v3 > bv) { bv = v3; bi = i0 + 3; }
    }
    int cur = warp_argmax_redux(bv, bi);

    // S-row ring, depth 3 (len >= 512 guaranteed, so initial fills are in-range)
    float4 ra = *(const float4*)(S + (size_t)(len - 1) * Csz + i0);
    float4 rb = *(const float4*)(S + (size_t)(len - 2) * Csz + i0);
    float4 rc = *(const float4*)(S + (size_t)(len - 3) * Csz + i0);
    for (int l = len - 1; l >= 1; --l) {
        float4 rd;
        if (l - 3 >= 0) rd = *(const float4*)(S + (size_t)(l - 3) * Csz + i0);
        if (lane == 0) orow[l] = (float)cur;
        float4 t = *(const float4*)(Tt + cur * Csz + i0);
        float v0 = ra.x + t.x, v1 = ra.y + t.y, v2 = ra.z + t.z, v3 = ra.w + t.w;
        bv = v0; bi = i0;
        if (v1 > bv) { bv = v1; bi = i0 + 1; }
        if (v2 > bv) { bv = v2; bi = i0 + 2; }
        if (v3 > bv) { bv = v3; bi = i0 + 3; }
        cur = warp_argmax_redux(bv, bi);
        ra = rb; rb = rc; rc = rd;
    }
    if (lane == 0) orow[0] = (float)cur;
}

// ---------------- launch ----------------
extern "C" void kernel_launch(void* const* d_in, const int* in_sizes, int n_in,
                              void* d_out, int out_size)
{
    const float* x = nullptr;
    const float* W = nullptr;
    const float* bias = nullptr;
    const float* trans = nullptr;
    const unsigned char* candA = nullptr;
    const unsigned char* candB = nullptr;
    for (int i = 0; i < n_in; ++i) {
        long long s = in_sizes[i];
        if      (s == (long long)Bsz * Lsz * Dsz) x = (const float*)d_in[i];
        else if (s == (long long)Dsz * Csz)       W = (const float*)d_in[i];
        else if (s == Csz)                        bias = (const float*)d_in[i];
        else if (s == Csz * Csz)                  trans = (const float*)d_in[i];
        else if (s == (long long)Bsz * Lsz) {
            if (!candA) candA = (const unsigned char*)d_in[i];
            else        candB = (const unsigned char*)d_in[i];
        }
    }
    float* out = (float*)d_out;

    cudaFuncSetAttribute(backtrack_kernel,
                         cudaFuncAttributeMaxDynamicSharedMemorySize, 128 * 128 * 4);

    detect_kernel<<<1, 256>>>(candA, candB);
    len_kernel<<<Bsz, 256>>>(candA, candB);
    prep_kernel<<<Csz * Csz / 256, 256>>>(trans);
    gemm_kernel<<<(Bsz * Lsz) / 128, 256>>>(x, W, bias);
    forward_kernel<<<Bsz, 128>>>(trans);
    backtrack_kernel<<<Bsz / 8, 256, 128 * 128 * 4>>>(out);
}

// round 13
// speedup vs baseline: 1.8088x; 1.0716x over previous
#include <cuda_runtime.h>
#include <cuda_bf16.h>

#define Bsz 64
#define Lsz 1024
#define Dsz 1024
#define Csz 128          // NUM_CLASS + 2
#define STOPTAG 127

// ---------------- scratch (device globals; no allocation allowed) ----------------
__device__ float g_emis[(size_t)Bsz * Lsz * Csz];            // 32 MB
__device__ float g_scores[(size_t)Bsz * (Lsz + 1) * Csz];    // 33.6 MB
__device__ float g_Tt[Csz * Csz];                            // 64 KB transposed T
__device__ int   g_len[Bsz];
__device__ int   g_sel;
__device__ int   g_width;

// ---------------- identify the mask among the two 65536-elem inputs ----------------
__global__ void detect_kernel(const unsigned char* A, const unsigned char* B) {
    __shared__ int bad[6];              // [cand*3 + w], w: 0=u64, 1=u32/f32, 2=u8
    int tid = threadIdx.x;
    if (tid < 6) bad[tid] = 0;
    __syncthreads();
    for (int cand = 0; cand < 2; ++cand) {
        const unsigned char* P = cand ? B : A;
        if (!P) { if (tid == 0) { bad[cand*3+0] = bad[cand*3+1] = bad[cand*3+2] = 1; } continue; }
        const unsigned long long* p8 = (const unsigned long long*)P;
        const unsigned* p4 = (const unsigned*)P;
        for (int i = tid; i < 1024; i += 256) {
            if (p8[i] > 1ull) atomicOr(&bad[cand*3+0], 1);
            unsigned v4 = p4[i];
            if (v4 != 0u && v4 != 1u && v4 != 0x3F800000u) atomicOr(&bad[cand*3+1], 1);
            if (P[i] > 1) atomicOr(&bad[cand*3+2], 1);
        }
    }
    __syncthreads();
    if (tid == 0) {
        int sel = 0, width = 1;
        bool done = false;
        for (int cand = 0; cand < 2 && !done; ++cand) {
            if      (!bad[cand*3+0]) { sel = cand; width = 8; done = true; }
            else if (!bad[cand*3+1]) { sel = cand; width = 4; done = true; }
            else if (!bad[cand*3+2]) { sel = cand; width = 1; done = true; }
        }
        g_sel = sel; g_width = width;
    }
}

// ---------------- sequence lengths ----------------
__global__ void len_kernel(const unsigned char* A, const unsigned char* B) {
    const unsigned char* M = g_sel ? B : A;
    const int w = g_width;
    const int b = blockIdx.x, tid = threadIdx.x;
    int cnt = 0;
    if (w == 8) {
        const unsigned long long* p = ((const unsigned long long*)M) + (size_t)b * Lsz;
        for (int i = tid; i < Lsz; i += 256) cnt += (p[i] != 0ull) ? 1 : 0;
    } else if (w == 4) {
        const unsigned* p = ((const unsigned*)M) + (size_t)b * Lsz;
        for (int i = tid; i < Lsz; i += 256) cnt += (p[i] != 0u) ? 1 : 0;
    } else {
        const unsigned char* p = M + (size_t)b * Lsz;
        for (int i = tid; i < Lsz; i += 256) cnt += (p[i] != 0) ? 1 : 0;
    }
    #pragma unroll
    for (int off = 16; off; off >>= 1) cnt += __shfl_xor_sync(0xffffffffu, cnt, off);
    __shared__ int sr[8];
    if ((tid & 31) == 0) sr[tid >> 5] = cnt;
    __syncthreads();
    if (tid == 0) {
        int s = 0;
        #pragma unroll
        for (int i = 0; i < 8; ++i) s += sr[i];
        g_len[b] = s;
    }
}

// ---------------- transpose T: g_Tt[cur][prev] = T[prev][cur] ----------------
__global__ void prep_kernel(const float* __restrict__ trans) {
    int idx = blockIdx.x * 256 + threadIdx.x;
    int p = idx >> 7, cu = idx & 127;
    g_Tt[cu * Csz + p] = trans[idx];
}

// ---------------- GEMM (round-6 version, verbatim) ----------------
#define FMA2(d, a, b) asm("fma.rn.f32x2 %0, %1, %2, %0;" : "+l"(d) : "l"(a), "l"(b))
#define PACK2(d, s)   asm("mov.b64 %0, {%1, %1};" : "=l"(d) : "f"(s))
#define PACKLH(d, lo, hi) asm("mov.b64 %0, {%1, %2};" : "=l"(d) : "f"(lo), "f"(hi))
#define UNPACK2(lo, hi, s) asm("mov.b64 {%0, %1}, %2;" : "=f"(lo), "=f"(hi) : "l"(s))
#define ADD2(d, a, b) asm("add.rn.f32x2 %0, %1, %2;" : "=l"(d) : "l"(a), "l"(b))

__global__ __launch_bounds__(256, 2) void gemm_kernel(
    const float* __restrict__ x, const float* __restrict__ W,
    const float* __restrict__ bias)
{
    __shared__ __align__(16) float As[2][16][132];   // [k][m], padded
    __shared__ __align__(16) float Bs[2][16][128];   // [k][n]

    const int tid = threadIdx.x;
    const int tx = tid & 15;
    const int ty = tid >> 4;
    const size_t m_base = (size_t)blockIdx.x * 128;

    const int rA0 = tid >> 2,         qA0 = tid & 3;
    const int rA1 = (tid + 256) >> 2, qA1 = tid & 3;
    const int rB0 = tid >> 5,         cB0 = tid & 31;
    const int rB1 = (tid + 256) >> 5, cB1 = tid & 31;

    unsigned long long acc[4][8];
    #pragma unroll
    for (int i = 0; i < 4; ++i)
        #pragma unroll
        for (int j = 0; j < 8; ++j) acc[i][j] = 0ull;

    {
        float4 va0 = *(const float4*)(x + (m_base + rA0) * Dsz + (qA0 << 2));
        float4 va1 = *(const float4*)(x + (m_base + rA1) * Dsz + (qA1 << 2));
        float4 vb0 = *(const float4*)(W + (size_t)rB0 * Csz + (cB0 << 2));
        float4 vb1 = *(const float4*)(W + (size_t)rB1 * Csz + (cB1 << 2));
        As[0][qA0 * 4 + 0][rA0] = va0.x; As[0][qA0 * 4 + 1][rA0] = va0.y;
        As[0][qA0 * 4 + 2][rA0] = va0.z; As[0][qA0 * 4 + 3][rA0] = va0.w;
        As[0][qA1 * 4 + 0][rA1] = va1.x; As[0][qA1 * 4 + 1][rA1] = va1.y;
        As[0][qA1 * 4 + 2][rA1] = va1.z; As[0][qA1 * 4 + 3][rA1] = va1.w;
        *(float4*)&Bs[0][rB0][cB0 << 2] = vb0;
        *(float4*)&Bs[0][rB1][cB1 << 2] = vb1;
    }
    __syncthreads();

    const int KT = Dsz / 16;   // 64
    float4 va0, va1, vb0, vb1;
    for (int kt = 0; kt < KT; ++kt) {
        const int buf = kt & 1;
        if (kt < KT - 1) {
            const int k0 = (kt + 1) * 16;
            va0 = *(const float4*)(x + (m_base + rA0) * Dsz + k0 + (qA0 << 2));
            va1 = *(const float4*)(x + (m_base + rA1) * Dsz + k0 + (qA1 << 2));
            vb0 = *(const float4*)(W + (size_t)(k0 + rB0) * Csz + (cB0 << 2));
            vb1 = *(const float4*)(W + (size_t)(k0 + rB1) * Csz + (cB1 << 2));
        }
        #pragma unroll
        for (int k = 0; k < 16; ++k) {
            const float* ap = &As[buf][k][ty * 8];
            ulonglong2 a01 = *(const ulonglong2*)ap;
            ulonglong2 a23 = *(const ulonglong2*)(ap + 4);
            const float* bp = &Bs[buf][k][tx * 8];
            float4 b03 = *(const float4*)bp;
            float4 b47 = *(const float4*)(bp + 4);
            float bv[8] = {b03.x, b03.y, b03.z, b03.w, b47.x, b47.y, b47.z, b47.w};
            #pragma unroll
            for (int j = 0; j < 8; ++j) {
                unsigned long long bb;
                PACK2(bb, bv[j]);
                FMA2(acc[0][j], a01.x, bb);
                FMA2(acc[1][j], a01.y, bb);
                FMA2(acc[2][j], a23.x, bb);
                FMA2(acc[3][j], a23.y, bb);
            }
        }
        if (kt < KT - 1) {
            const int nb = buf ^ 1;
            __syncthreads();
            As[nb][qA0 * 4 + 0][rA0] = va0.x; As[nb][qA0 * 4 + 1][rA0] = va0.y;
            As[nb][qA0 * 4 + 2][rA0] = va0.z; As[nb][qA0 * 4 + 3][rA0] = va0.w;
            As[nb][qA1 * 4 + 0][rA1] = va1.x; As[nb][qA1 * 4 + 1][rA1] = va1.y;
            As[nb][qA1 * 4 + 2][rA1] = va1.z; As[nb][qA1 * 4 + 3][rA1] = va1.w;
            *(float4*)&Bs[nb][rB0][cB0 << 2] = vb0;
            *(float4*)&Bs[nb][rB1][cB1 << 2] = vb1;
            __syncthreads();
        }
    }

    float bvv[8];
    #pragma unroll
    for (int j = 0; j < 8; ++j) bvv[j] = bias[tx * 8 + j];
    #pragma unroll
    for (int i = 0; i < 4; ++i) {
        float lo[8], hi[8];
        #pragma unroll
        for (int j = 0; j < 8; ++j) {
            UNPACK2(lo[j], hi[j], acc[i][j]);
            lo[j] += bvv[j]; hi[j] += bvv[j];
        }
        size_t me = m_base + ty * 8 + 2 * i;
        float* oe = g_emis + me * Csz + tx * 8;
        float* oo = g_emis + (me + 1) * Csz + tx * 8;
        *(float4*)oe       = make_float4(lo[0], lo[1], lo[2], lo[3]);
        *(float4*)(oe + 4) = make_float4(lo[4], lo[5], lo[6], lo[7]);
        *(float4*)oo       = make_float4(hi[0], hi[1], hi[2], hi[3]);
        *(float4*)(oo + 4) = make_float4(hi[4], hi[5], hi[6], hi[7]);
    }
}

// ---------------- Viterbi forward v4b: packed ADD2 + scalar max ----------------
// Thread c owns cur-state c. T column stored as 64 packed pairs
// tp[i] = {T[2i][c], T[2i+1][c]}. Inner loop: 64 ADD2 (fma pipe, exact rn per
// lane) + 128 scalar FMNMX into 8 accumulator chains. Unpack of the packed
// sum is register renaming (free). Bitwise identical to scalar scan.
__global__ __launch_bounds__(128, 1) void forward_kernel(const float* __restrict__ trans)
{
    __shared__ __align__(16) float sbuf[264];   // two buffers, 132-float pitch
    const int b = blockIdx.x;
    const int c = threadIdx.x;
    const int len = g_len[b];

    unsigned long long tp[64];
    #pragma unroll
    for (int i = 0; i < 64; ++i) {
        float lo = trans[(2 * i) * Csz + c];
        float hi = trans[(2 * i + 1) * Csz + c];
        PACKLH(tp[i], lo, hi);
    }

    float cur = 0.0f;
    const float* eptr = g_emis + (size_t)b * Lsz * Csz + c;
    float* scrp = g_scores + (size_t)b * (Lsz + 1) * Csz + c;

    // emission prefetch ring, depth 2 (covers ~250-cyc L2 hit)
    float e0 = eptr[0];
    float e1 = eptr[Csz];

    int par = 0;
    for (int l = 0; l < len; ++l) {
        float* sb = sbuf + (par ? 132 : 0);
        sb[c] = cur;
        scrp[(size_t)l * Csz] = cur;            // entry scores S_l
        __syncthreads();
        float e = e0;
        e0 = e1;
        if (l + 2 < len) e1 = eptr[(size_t)(l + 2) * Csz];
        float m0 = -3.4e38f, m1 = -3.4e38f, m2 = -3.4e38f, m3 = -3.4e38f;
        float m4 = -3.4e38f, m5 = -3.4e38f, m6 = -3.4e38f, m7 = -3.4e38f;
        #pragma unroll
        for (int j = 0; j < 32; j += 2) {
            ulonglong2 sA = *(const ulonglong2*)(sb + j * 4);       // prev pairs 2j,2j+1
            ulonglong2 sB = *(const ulonglong2*)(sb + j * 4 + 4);   // prev pairs 2j+2,2j+3
            unsigned long long t0, t1, t2, t3;
            ADD2(t0, sA.x, tp[2 * j + 0]);
            ADD2(t1, sA.y, tp[2 * j + 1]);
            ADD2(t2, sB.x, tp[2 * j + 2]);
            ADD2(t3, sB.y, tp[2 * j + 3]);
            float a0, a1, b0, b1, c0, c1, d0, d1;
            UNPACK2(a0, a1, t0);
            UNPACK2(b0, b1, t1);
            UNPACK2(c0, c1, t2);
            UNPACK2(d0, d1, t3);
            m0 = fmaxf(m0, a0); m1 = fmaxf(m1, a1);
            m2 = fmaxf(m2, b0); m3 = fmaxf(m3, b1);
            m4 = fmaxf(m4, c0); m5 = fmaxf(m5, c1);
            m6 = fmaxf(m6, d0); m7 = fmaxf(m7, d1);
        }
        float ma = fmaxf(fmaxf(m0, m1), fmaxf(m2, m3));
        float mb = fmaxf(fmaxf(m4, m5), fmaxf(m6, m7));
        cur = fmaxf(ma, mb) + e;
        par ^= 1;
    }
    scrp[(size_t)len * Csz] = cur;              // final scores (pre STOP-transition)
}

// ---------------- backtrack (R7 version, verbatim): smem Tt + redux argmax ----------------
__device__ __forceinline__ unsigned orderable(float f) {
    unsigned u = __float_as_uint(f);
    return (u & 0x80000000u) ? ~u : (u | 0x80000000u);
}

__device__ __forceinline__ int warp_argmax_redux(float bv, int bi) {
    unsigned u = orderable(bv);
    unsigned mx = __reduce_max_sync(0xffffffffu, u);
    unsigned cand = (u == mx) ? (unsigned)bi : 0xffffffffu;
    return (int)__reduce_min_sync(0xffffffffu, cand);    // first occurrence
}

__global__ __launch_bounds__(256, 1) void backtrack_kernel(float* __restrict__ out)
{
    extern __shared__ __align__(16) float Tt[];   // [128][128] = 64 KB
    const int tid = threadIdx.x;
    for (int idx = tid; idx < 128 * 128; idx += 256) Tt[idx] = g_Tt[idx];
    __syncthreads();

    const int w = tid >> 5, lane = tid & 31;
    const int b = blockIdx.x * 8 + w;
    const int len = g_len[b];
    const float* S = g_scores + (size_t)b * (Lsz + 1) * Csz;
    float* orow = out + (size_t)b * Lsz;
    const int i0 = lane * 4;

    for (int l = len + lane; l < Lsz; l += 32) orow[l] = 0.0f;

    float4 fv = *(const float4*)(S + (size_t)len * Csz + i0);
    float4 tv = *(const float4*)(Tt + STOPTAG * Csz + i0);
    float bv; int bi;
    {
        float v0 = fv.x + tv.x, v1 = fv.y + tv.y, v2 = fv.z + tv.z, v3 = fv.w + tv.w;
        bv = v0; bi = i0;
        if (v1 > bv) { bv = v1; bi = i0 + 1; }
        if (v2 > bv) { bv = v2; bi = i0 + 2; }
        if (v3 > bv) { bv = v3; bi = i0 + 3; }
    }
    int cur = warp_argmax_redux(bv, bi);

    float4 r = *(const float4*)(S + (size_t)(len - 1) * Csz + i0);
    for (int l = len - 1; l >= 1; --l) {
        float4 rn;
        if (l > 1) rn = *(const float4*)(S + (size_t)(l - 1) * Csz + i0);
        if (lane == 0) orow[l] = (float)cur;
        float4 t = *(const float4*)(Tt + cur * Csz + i0);
        float v0 = r.x + t.x, v1 = r.y + t.y, v2 = r.z + t.z, v3 = r.w + t.w;
        bv = v0; bi = i0;
        if (v1 > bv) { bv = v1; bi = i0 + 1; }
        if (v2 > bv) { bv = v2; bi = i0 + 2; }
        if (v3 > bv) { bv = v3; bi = i0 + 3; }
        cur = warp_argmax_redux(bv, bi);
        if (l > 1) r = rn;
    }
    if (lane == 0) orow[0] = (float)cur;
}

// ---------------- launch ----------------
extern "C" void kernel_launch(void* const* d_in, const int* in_sizes, int n_in,
                              void* d_out, int out_size)
{
    const float* x = nullptr;
    const float* W = nullptr;
    const float* bias = nullptr;
    const float* trans = nullptr;
    const unsigned char* candA = nullptr;
    const unsigned char* candB = nullptr;
    for (int i = 0; i < n_in; ++i) {
        long long s = in_sizes[i];
        if      (s == (long long)Bsz * Lsz * Dsz) x = (const float*)d_in[i];
        else if (s == (long long)Dsz * Csz)       W = (const float*)d_in[i];
        else if (s == Csz)                        bias = (const float*)d_in[i];
        else if (s == Csz * Csz)                  trans = (const float*)d_in[i];
        else if (s == (long long)Bsz * Lsz) {
            if (!candA) candA = (const unsigned char*)d_in[i];
            else        candB = (const unsigned char*)d_in[i];
        }
    }
    float* out = (float*)d_out;

    cudaFuncSetAttribute(backtrack_kernel,
                         cudaFuncAttributeMaxDynamicSharedMemorySize, 128 * 128 * 4);

    detect_kernel<<<1, 256>>>(candA, candB);
    len_kernel<<<Bsz, 256>>>(candA, candB);
    prep_kernel<<<Csz * Csz / 256, 256>>>(trans);
    gemm_kernel<<<(Bsz * Lsz) / 128, 256>>>(x, W, bias);
    forward_kernel<<<Bsz, 128>>>(trans);
    backtrack_kernel<<<Bsz / 8, 256, 128 * 128 * 4>>>(out);
}

// round 14
// speedup vs baseline: 1.8685x; 1.0330x over previous
#include <cuda_runtime.h>
#include <cuda_bf16.h>

#define Bsz 64
#define Lsz 1024
#define Dsz 1024
#define Csz 128          // NUM_CLASS + 2
#define STOPTAG 127

// ---------------- scratch (device globals; no allocation allowed) ----------------
__device__ float g_emis[(size_t)Bsz * Lsz * Csz];            // 32 MB
__device__ float g_scores[(size_t)Bsz * (Lsz + 1) * Csz];    // 33.6 MB
__device__ float g_Tt[Csz * Csz];                            // 64 KB transposed T
__device__ int   g_len[Bsz];

// ---------------- GEMM (round-6 version, verbatim; 387us anchored) ----------------
#define FMA2(d, a, b) asm("fma.rn.f32x2 %0, %1, %2, %0;" : "+l"(d) : "l"(a), "l"(b))
#define PACK2(d, s)   asm("mov.b64 %0, {%1, %1};" : "=l"(d) : "f"(s))
#define UNPACK2(lo, hi, s) asm("mov.b64 {%0, %1}, %2;" : "=f"(lo), "=f"(hi) : "l"(s))

__global__ __launch_bounds__(256, 2) void gemm_kernel(
    const float* __restrict__ x, const float* __restrict__ W,
    const float* __restrict__ bias)
{
    __shared__ __align__(16) float As[2][16][132];   // [k][m], padded
    __shared__ __align__(16) float Bs[2][16][128];   // [k][n]

    const int tid = threadIdx.x;
    const int tx = tid & 15;
    const int ty = tid >> 4;
    const size_t m_base = (size_t)blockIdx.x * 128;

    const int rA0 = tid >> 2,         qA0 = tid & 3;
    const int rA1 = (tid + 256) >> 2, qA1 = tid & 3;
    const int rB0 = tid >> 5,         cB0 = tid & 31;
    const int rB1 = (tid + 256) >> 5, cB1 = tid & 31;

    unsigned long long acc[4][8];
    #pragma unroll
    for (int i = 0; i < 4; ++i)
        #pragma unroll
        for (int j = 0; j < 8; ++j) acc[i][j] = 0ull;

    {
        float4 va0 = *(const float4*)(x + (m_base + rA0) * Dsz + (qA0 << 2));
        float4 va1 = *(const float4*)(x + (m_base + rA1) * Dsz + (qA1 << 2));
        float4 vb0 = *(const float4*)(W + (size_t)rB0 * Csz + (cB0 << 2));
        float4 vb1 = *(const float4*)(W + (size_t)rB1 * Csz + (cB1 << 2));
        As[0][qA0 * 4 + 0][rA0] = va0.x; As[0][qA0 * 4 + 1][rA0] = va0.y;
        As[0][qA0 * 4 + 2][rA0] = va0.z; As[0][qA0 * 4 + 3][rA0] = va0.w;
        As[0][qA1 * 4 + 0][rA1] = va1.x; As[0][qA1 * 4 + 1][rA1] = va1.y;
        As[0][qA1 * 4 + 2][rA1] = va1.z; As[0][qA1 * 4 + 3][rA1] = va1.w;
        *(float4*)&Bs[0][rB0][cB0 << 2] = vb0;
        *(float4*)&Bs[0][rB1][cB1 << 2] = vb1;
    }
    __syncthreads();

    const int KT = Dsz / 16;   // 64
    float4 va0, va1, vb0, vb1;
    for (int kt = 0; kt < KT; ++kt) {
        const int buf = kt & 1;
        if (kt < KT - 1) {
            const int k0 = (kt + 1) * 16;
            va0 = *(const float4*)(x + (m_base + rA0) * Dsz + k0 + (qA0 << 2));
            va1 = *(const float4*)(x + (m_base + rA1) * Dsz + k0 + (qA1 << 2));
            vb0 = *(const float4*)(W + (size_t)(k0 + rB0) * Csz + (cB0 << 2));
            vb1 = *(const float4*)(W + (size_t)(k0 + rB1) * Csz + (cB1 << 2));
        }
        #pragma unroll
        for (int k = 0; k < 16; ++k) {
            const float* ap = &As[buf][k][ty * 8];
            ulonglong2 a01 = *(const ulonglong2*)ap;
            ulonglong2 a23 = *(const ulonglong2*)(ap + 4);
            const float* bp = &Bs[buf][k][tx * 8];
            float4 b03 = *(const float4*)bp;
            float4 b47 = *(const float4*)(bp + 4);
            float bv[8] = {b03.x, b03.y, b03.z, b03.w, b47.x, b47.y, b47.z, b47.w};
            #pragma unroll
            for (int j = 0; j < 8; ++j) {
                unsigned long long bb;
                PACK2(bb, bv[j]);
                FMA2(acc[0][j], a01.x, bb);
                FMA2(acc[1][j], a01.y, bb);
                FMA2(acc[2][j], a23.x, bb);
                FMA2(acc[3][j], a23.y, bb);
            }
        }
        if (kt < KT - 1) {
            const int nb = buf ^ 1;
            __syncthreads();
            As[nb][qA0 * 4 + 0][rA0] = va0.x; As[nb][qA0 * 4 + 1][rA0] = va0.y;
            As[nb][qA0 * 4 + 2][rA0] = va0.z; As[nb][qA0 * 4 + 3][rA0] = va0.w;
            As[nb][qA1 * 4 + 0][rA1] = va1.x; As[nb][qA1 * 4 + 1][rA1] = va1.y;
            As[nb][qA1 * 4 + 2][rA1] = va1.z; As[nb][qA1 * 4 + 3][rA1] = va1.w;
            *(float4*)&Bs[nb][rB0][cB0 << 2] = vb0;
            *(float4*)&Bs[nb][rB1][cB1 << 2] = vb1;
            __syncthreads();
        }
    }

    float bvv[8];
    #pragma unroll
    for (int j = 0; j < 8; ++j) bvv[j] = bias[tx * 8 + j];
    #pragma unroll
    for (int i = 0; i < 4; ++i) {
        float lo[8], hi[8];
        #pragma unroll
        for (int j = 0; j < 8; ++j) {
            UNPACK2(lo[j], hi[j], acc[i][j]);
            lo[j] += bvv[j]; hi[j] += bvv[j];
        }
        size_t me = m_base + ty * 8 + 2 * i;
        float* oe = g_emis + me * Csz + tx * 8;
        float* oo = g_emis + (me + 1) * Csz + tx * 8;
        *(float4*)oe       = make_float4(lo[0], lo[1], lo[2], lo[3]);
        *(float4*)(oe + 4) = make_float4(lo[4], lo[5], lo[6], lo[7]);
        *(float4*)oo       = make_float4(hi[0], hi[1], hi[2], hi[3]);
        *(float4*)(oo + 4) = make_float4(hi[4], hi[5], hi[6], hi[7]);
    }
}

// ---------------- fused detect + length (one kernel; block b re-derives dtype) ----------------
__global__ void lenfused_kernel(const unsigned char* A, const unsigned char* B) {
    __shared__ int bad[6];              // [cand*3 + w], w: 0=u64, 1=u32/f32, 2=u8
    __shared__ int sr[8];
    const int b = blockIdx.x, tid = threadIdx.x;
    if (tid < 6) bad[tid] = 0;
    __syncthreads();
    // detect on row 0 of both candidates (redundant per block; ~2KB reads)
    for (int cand = 0; cand < 2; ++cand) {
        const unsigned char* P = cand ? B : A;
        if (!P) { if (tid == 0) { bad[cand*3+0] = bad[cand*3+1] = bad[cand*3+2] = 1; } continue; }
        const unsigned long long* p8 = (const unsigned long long*)P;
        const unsigned* p4 = (const unsigned*)P;
        for (int i = tid; i < 1024; i += 256) {
            if (p8[i] > 1ull) atomicOr(&bad[cand*3+0], 1);
            unsigned v4 = p4[i];
            if (v4 != 0u && v4 != 1u && v4 != 0x3F800000u) atomicOr(&bad[cand*3+1], 1);
            if (P[i] > 1) atomicOr(&bad[cand*3+2], 1);
        }
    }
    __syncthreads();
    int sel = 0, width = 1;
    {
        bool done = false;
        for (int cand = 0; cand < 2 && !done; ++cand) {
            if      (!bad[cand*3+0]) { sel = cand; width = 8; done = true; }
            else if (!bad[cand*3+1]) { sel = cand; width = 4; done = true; }
            else if (!bad[cand*3+2]) { sel = cand; width = 1; done = true; }
        }
    }
    const unsigned char* M = sel ? B : A;
    int cnt = 0;
    if (width == 8) {
        const unsigned long long* p = ((const unsigned long long*)M) + (size_t)b * Lsz;
        for (int i = tid; i < Lsz; i += 256) cnt += (p[i] != 0ull) ? 1 : 0;
    } else if (width == 4) {
        const unsigned* p = ((const unsigned*)M) + (size_t)b * Lsz;
        for (int i = tid; i < Lsz; i += 256) cnt += (p[i] != 0u) ? 1 : 0;
    } else {
        const unsigned char* p = M + (size_t)b * Lsz;
        for (int i = tid; i < Lsz; i += 256) cnt += (p[i] != 0) ? 1 : 0;
    }
    #pragma unroll
    for (int off = 16; off; off >>= 1) cnt += __shfl_xor_sync(0xffffffffu, cnt, off);
    if ((tid & 31) == 0) sr[tid >> 5] = cnt;
    __syncthreads();
    if (tid == 0) {
        int s = 0;
        #pragma unroll
        for (int i = 0; i < 8; ++i) s += sr[i];
        g_len[b] = s;
    }
}

// ---------------- transpose T: g_Tt[cur][prev] = T[prev][cur] ----------------
__global__ void prep_kernel(const float* __restrict__ trans) {
    int idx = blockIdx.x * 256 + threadIdx.x;
    int p = idx >> 7, cu = idx & 127;
    g_Tt[cu * Csz + p] = trans[idx];
}

// ---------------- Viterbi forward (R7-best version, verbatim) ----------------
__global__ __launch_bounds__(128, 1) void forward_kernel(const float* __restrict__ trans)
{
    __shared__ __align__(16) float sbuf[264];   // two buffers, 132-float pitch
    const int b = blockIdx.x;
    const int c = threadIdx.x;
    const int len = g_len[b];

    float treg[128];                            // treg[p] = T[p][c]
    #pragma unroll
    for (int p = 0; p < 128; ++p) treg[p] = trans[p * Csz + c];

    float cur = 0.0f;
    const float* eptr = g_emis + (size_t)b * Lsz * Csz + c;
    float* scrp = g_scores + (size_t)b * (Lsz + 1) * Csz + c;

    float e_next = eptr[0];                     // depth-1 emission prefetch
    int par = 0;
    for (int l = 0; l < len; ++l) {
        float* sb = sbuf + (par ? 132 : 0);
        sb[c] = cur;
        scrp[(size_t)l * Csz] = cur;            // entry scores S_l
        __syncthreads();
        float e = e_next;
        if (l + 1 < len) e_next = eptr[(size_t)(l + 1) * Csz];
        float m0 = -3.4e38f, m1 = -3.4e38f, m2 = -3.4e38f, m3 = -3.4e38f;
        #pragma unroll
        for (int p = 0; p < 128; p += 4) {
            float4 ss = *(const float4*)(sb + p);
            m0 = fmaxf(m0, ss.x + treg[p + 0]);
            m1 = fmaxf(m1, ss.y + treg[p + 1]);
            m2 = fmaxf(m2, ss.z + treg[p + 2]);
            m3 = fmaxf(m3, ss.w + treg[p + 3]);
        }
        cur = fmaxf(fmaxf(m0, m1), fmaxf(m2, m3)) + e;
        par ^= 1;
    }
    scrp[(size_t)len * Csz] = cur;              // final scores (pre STOP-transition)
}

// ---------------- backtrack (R7 version, verbatim): smem Tt + redux argmax ----------------
__device__ __forceinline__ unsigned orderable(float f) {
    unsigned u = __float_as_uint(f);
    return (u & 0x80000000u) ? ~u : (u | 0x80000000u);
}

__device__ __forceinline__ int warp_argmax_redux(float bv, int bi) {
    unsigned u = orderable(bv);
    unsigned mx = __reduce_max_sync(0xffffffffu, u);
    unsigned cand = (u == mx) ? (unsigned)bi : 0xffffffffu;
    return (int)__reduce_min_sync(0xffffffffu, cand);    // first occurrence
}

__global__ __launch_bounds__(256, 1) void backtrack_kernel(float* __restrict__ out)
{
    extern __shared__ __align__(16) float Tt[];   // [128][128] = 64 KB
    const int tid = threadIdx.x;
    for (int idx = tid; idx < 128 * 128; idx += 256) Tt[idx] = g_Tt[idx];
    __syncthreads();

    const int w = tid >> 5, lane = tid & 31;
    const int b = blockIdx.x * 8 + w;
    const int len = g_len[b];
    const float* S = g_scores + (size_t)b * (Lsz + 1) * Csz;
    float* orow = out + (size_t)b * Lsz;
    const int i0 = lane * 4;

    for (int l = len + lane; l < Lsz; l += 32) orow[l] = 0.0f;

    float4 fv = *(const float4*)(S + (size_t)len * Csz + i0);
    float4 tv = *(const float4*)(Tt + STOPTAG * Csz + i0);
    float bv; int bi;
    {
        float v0 = fv.x + tv.x, v1 = fv.y + tv.y, v2 = fv.z + tv.z, v3 = fv.w + tv.w;
        bv = v0; bi = i0;
        if (v1 > bv) { bv = v1; bi = i0 + 1; }
        if (v2 > bv) { bv = v2; bi = i0 + 2; }
        if (v3 > bv) { bv = v3; bi = i0 + 3; }
    }
    int cur = warp_argmax_redux(bv, bi);

    float4 r = *(const float4*)(S + (size_t)(len - 1) * Csz + i0);
    for (int l = len - 1; l >= 1; --l) {
        float4 rn;
        if (l > 1) rn = *(const float4*)(S + (size_t)(l - 1) * Csz + i0);
        if (lane == 0) orow[l] = (float)cur;
        float4 t = *(const float4*)(Tt + cur * Csz + i0);
        float v0 = r.x + t.x, v1 = r.y + t.y, v2 = r.z + t.z, v3 = r.w + t.w;
        bv = v0; bi = i0;
        if (v1 > bv) { bv = v1; bi = i0 + 1; }
        if (v2 > bv) { bv = v2; bi = i0 + 2; }
        if (v3 > bv) { bv = v3; bi = i0 + 3; }
        cur = warp_argmax_redux(bv, bi);
        if (l > 1) r = rn;
    }
    if (lane == 0) orow[0] = (float)cur;
}

// ---------------- launch ----------------
// Order chosen so forward_kernel lands in the ncu capture slot (-s 5 -c 1):
// two harness launches precede ours; gemm(3rd), lenfused(4th), prep(5th),
// forward(6th <- captured), backtrack(7th).
extern "C" void kernel_launch(void* const* d_in, const int* in_sizes, int n_in,
                              void* d_out, int out_size)
{
    const float* x = nullptr;
    const float* W = nullptr;
    const float* bias = nullptr;
    const float* trans = nullptr;
    const unsigned char* candA = nullptr;
    const unsigned char* candB = nullptr;
    for (int i = 0; i < n_in; ++i) {
        long long s = in_sizes[i];
        if      (s == (long long)Bsz * Lsz * Dsz) x = (const float*)d_in[i];
        else if (s == (long long)Dsz * Csz)       W = (const float*)d_in[i];
        else if (s == Csz)                        bias = (const float*)d_in[i];
        else if (s == Csz * Csz)                  trans = (const float*)d_in[i];
        else if (s == (long long)Bsz * Lsz) {
            if (!candA) candA = (const unsigned char*)d_in[i];
            else        candB = (const unsigned char*)d_in[i];
        }
    }
    float* out = (float*)d_out;

    cudaFuncSetAttribute(backtrack_kernel,
                         cudaFuncAttributeMaxDynamicSharedMemorySize, 128 * 128 * 4);

    gemm_kernel<<<(Bsz * Lsz) / 128, 256>>>(x, W, bias);
    lenfused_kernel<<<Bsz, 256>>>(candA, candB);
    prep_kernel<<<Csz * Csz / 256, 256>>>(trans);
    forward_kernel<<<Bsz, 128>>>(trans);
    backtrack_kernel<<<Bsz / 8, 256, 128 * 128 * 4>>>(out);
}